// round 10
// baseline (speedup 1.0000x reference)
#include <cuda_runtime.h>
#include <cuda_fp16.h>
#include <cstdint>

#define BATCH 512
#define NTOK  256
#define MTOT  (BATCH*NTOK)
#define NT2   (MTOT/256)

__device__ __half g_w[294912];
__device__ __half g_X [(size_t)MTOT*512];
__device__ __half g_Bg[(size_t)MTOT*128];
__device__ __half g_Cg[(size_t)MTOT*256];
__device__ __half g_G [(size_t)MTOT*256];
__device__ __half g_Bv[(size_t)MTOT*128];
__device__ __half g_Cv[(size_t)MTOT*256];
__device__ int    g_slot[MTOT];
__device__ int    g_cnt;
__device__ __half* g_bufs[6];

__constant__ int WOFF[9] = {0,65536,98304,131072,163840,196608,229376,262144,294912};

__global__ void convert_w(const float* w0,const float* w1,const float* w2,const float* w3,
                          const float* w4,const float* w5,const float* w6,const float* w7)
{
    int i = blockIdx.x*blockDim.x + threadIdx.x;
    if (i == 0) {
        g_cnt = 0;
        g_bufs[0]=g_X; g_bufs[1]=g_Bg; g_bufs[2]=g_Cg;
        g_bufs[3]=g_G; g_bufs[4]=g_Bv; g_bufs[5]=g_Cv;
    }
    if (i >= 294912) return;
    const float* p[8] = {w0,w1,w2,w3,w4,w5,w6,w7};
    int s = 0;
    while (i >= WOFF[s+1]) s++;
    g_w[i] = __float2half_rn(p[s][i - WOFF[s]]);
}

__global__ void __launch_bounds__(1024) stage1(const float* __restrict__ h0,
                                               const float* __restrict__ hT)
{
    __shared__ int flg[32], pre[32];
    int warp = threadIdx.x >> 5, lane = threadIdx.x & 31;
    int tok = blockIdx.x*32 + warp;
    const float4* p0 = (const float4*)(h0 + (size_t)tok*256);
    const float4* p1 = (const float4*)(hT + (size_t)tok*256);
    float4 a0 = p0[lane], a1 = p0[lane+32];
    float4 b0 = p1[lane], b1 = p1[lane+32];
    float s = a0.x+a0.y+a0.z+a0.w + a1.x+a1.y+a1.z+a1.w;
    #pragma unroll
    for (int o = 16; o > 0; o >>= 1) s += __shfl_xor_sync(0xffffffffu, s, o);
    int act = (s > 0.0f) ? 1 : 0;
    if (lane == 0) flg[warp] = act;
    __syncthreads();
    if (threadIdx.x == 0) {
        int tot = 0;
        for (int i = 0; i < 32; i++) { pre[i] = tot; tot += flg[i]; }
        flg[0] = atomicAdd(&g_cnt, tot);
    }
    __syncthreads();
    int slot = act ? (flg[0] + pre[warp]) : -1;
    if (lane == 0) g_slot[tok] = slot;
    if (act) {
        __half2* X = (__half2*)(g_X + (size_t)slot*512);
        X[lane*2+0]   = __floats2half2_rn(a0.x, a0.y);
        X[lane*2+1]   = __floats2half2_rn(a0.z, a0.w);
        X[64+lane*2]  = __floats2half2_rn(a1.x, a1.y);
        X[65+lane*2]  = __floats2half2_rn(a1.z, a1.w);
        X[128+lane*2] = __floats2half2_rn(b0.x, b0.y);
        X[129+lane*2] = __floats2half2_rn(b0.z, b0.w);
        X[192+lane*2] = __floats2half2_rn(b1.x, b1.y);
        X[193+lane*2] = __floats2half2_rn(b1.z, b1.w);
    }
}

__device__ __forceinline__ uint32_t s2u(const void* p) {
    uint32_t a;
    asm("{ .reg .u64 t; cvta.to.shared.u64 t, %1; cvt.u32.u64 %0, t; }" : "=r"(a) : "l"(p));
    return a;
}
#define CPA(d, s) asm volatile("cp.async.cg.shared.global [%0], [%1], 16;" :: "r"(d), "l"(s))
#define CPC() asm volatile("cp.async.commit_group;" ::: "memory")

#define LDA_S 88
#define LDB_S 136
#define SA_ST (256*LDA_S)
#define SB_ST (64*LDB_S)
#define SMEMB ((2*SA_ST + 2*SB_ST)*2)   // 124928 bytes

__device__ __forceinline__ void ldmA(uint32_t* a, uint32_t addr) {
    asm volatile("ldmatrix.sync.aligned.m8n8.x4.shared.b16 {%0,%1,%2,%3}, [%4];"
        : "=r"(a[0]), "=r"(a[1]), "=r"(a[2]), "=r"(a[3]) : "r"(addr));
}
__device__ __forceinline__ void ldmB4(uint32_t* b, uint32_t addr) {
    asm volatile("ldmatrix.sync.aligned.m8n8.x4.trans.shared.b16 {%0,%1,%2,%3}, [%4];"
        : "=r"(b[0]), "=r"(b[1]), "=r"(b[2]), "=r"(b[3]) : "r"(addr));
}
__device__ __forceinline__ void mma16816(float* d, const uint32_t* a,
                                         uint32_t b0, uint32_t b1) {
    asm volatile("mma.sync.aligned.m16n8k16.row.col.f32.f16.f16.f32 "
        "{%0,%1,%2,%3},{%4,%5,%6,%7},{%8,%9},{%0,%1,%2,%3};"
        : "+f"(d[0]), "+f"(d[1]), "+f"(d[2]), "+f"(d[3])
        : "r"(a[0]), "r"(a[1]), "r"(a[2]), "r"(a[3]), "r"(b0), "r"(b1));
}

// 256x128 CTA tile, 8 warps as 4m x 2n (warp tile 64x64), BK=64, 2-stage cp.async
__global__ void __launch_bounds__(256,1) gemm_k(
    int asel0, int aoff0, int lda0, int woff0, int K0, const float* b0p, int csel0, int act0,
    int asel1, int aoff1, int lda1, int woff1, int K1, const float* b1p, int csel1, int act1,
    int N)
{
    extern __shared__ __half sm[];
    __half* sA = sm;
    __half* sB = sm + 2*SA_ST;
    int m0 = blockIdx.x * 256;
    if (m0 >= g_cnt) return;

    int asel, aoff, lda, woff, K, csel, act; const float* bias;
    if (blockIdx.z == 0) { asel=asel0; aoff=aoff0; lda=lda0; woff=woff0; K=K0; bias=b0p; csel=csel0; act=act0; }
    else                 { asel=asel1; aoff=aoff1; lda=lda1; woff=woff1; K=K1; bias=b1p; csel=csel1; act=act1; }

    const __half* __restrict__ A = g_bufs[asel] + (size_t)m0*lda + aoff;
    const __half* __restrict__ W = g_w + woff;
    __half* __restrict__ Co = g_bufs[csel];
    const int n0 = blockIdx.y * 128;
    const int tid = threadIdx.x, warp = tid >> 5, lane = tid & 31;
    const int mw = (warp & 3) * 64;
    const int nw = (warp >> 2) * 64;
    const uint32_t sAu = s2u(sA), sBu = s2u(sB);

    float d[4][8][4];
    #pragma unroll
    for (int i = 0; i < 4; i++)
        #pragma unroll
        for (int j = 0; j < 8; j++)
            #pragma unroll
            for (int e = 0; e < 4; e++) d[i][j][e] = 0.0f;

    const int nk = K >> 6;

    #define LOAD_STAGE(st, kc) do {                                                  \
        int _k0 = (kc) * 64;                                                         \
        _Pragma("unroll")                                                            \
        for (int t = 0; t < 8; t++) {                                                \
            int idx = tid + t*256;                                                   \
            int r = idx >> 3, c8 = (idx & 7) * 8;                                    \
            CPA(sAu + ((st)*SA_ST + r*LDA_S + c8)*2, A + (size_t)r*lda + _k0 + c8);  \
        }                                                                            \
        _Pragma("unroll")                                                            \
        for (int t = 0; t < 4; t++) {                                                \
            int idx = tid + t*256;                                                   \
            int r = idx >> 4, c8 = (idx & 15) * 8;                                   \
            CPA(sBu + ((st)*SB_ST + r*LDB_S + c8)*2, W + (size_t)(_k0+r)*N + n0 + c8); \
        }                                                                            \
        CPC();                                                                       \
    } while (0)

    const uint32_t aRow = mw + (lane & 7) + ((lane & 8) ? 8 : 0);
    const uint32_t aCol = (lane & 16) ? 8 : 0;
    const uint32_t aBase = sAu + (aRow * LDA_S + aCol) * 2;
    // x4.trans B: lanes 0-7 k0-7/n+0, 8-15 k8-15/n+0, 16-23 k0-7/n+8, 24-31 k8-15/n+8
    const uint32_t bBase = sBu + ((lane & 15) * LDB_S + nw + (lane >> 4) * 8) * 2;

    LOAD_STAGE(0, 0);
    for (int k = 0; k < nk; k++) {
        if (k + 1 < nk) {
            LOAD_STAGE((k+1) & 1, k+1);
            asm volatile("cp.async.wait_group 1;" ::: "memory");
        } else {
            asm volatile("cp.async.wait_group 0;" ::: "memory");
        }
        __syncthreads();
        const uint32_t aS = aBase + ((k & 1) * SA_ST) * 2;
        const uint32_t bS = bBase + ((k & 1) * SB_ST) * 2;
        #pragma unroll
        for (int kk = 0; kk < 4; kk++) {
            uint32_t af[4][4], bq[4][4];
            #pragma unroll
            for (int i = 0; i < 4; i++)
                ldmA(af[i], aS + (i*16*LDA_S + kk*16) * 2);
            #pragma unroll
            for (int jj = 0; jj < 4; jj++)
                ldmB4(bq[jj], bS + (kk*16*LDB_S + jj*16) * 2);
            #pragma unroll
            for (int i = 0; i < 4; i++)
                #pragma unroll
                for (int jj = 0; jj < 4; jj++) {
                    mma16816(d[i][jj*2  ], af[i], bq[jj][0], bq[jj][1]);
                    mma16816(d[i][jj*2+1], af[i], bq[jj][2], bq[jj][3]);
                }
        }
        __syncthreads();
    }

    #pragma unroll
    for (int i = 0; i < 4; i++) {
        int row = m0 + mw + i*16 + (lane >> 2);
        #pragma unroll
        for (int j = 0; j < 8; j++) {
            int gcol = n0 + nw + j*8 + (lane & 3)*2;
            float2 bb = *(const float2*)&bias[gcol];
            float v0 = d[i][j][0] + bb.x, v1 = d[i][j][1] + bb.y;
            float v2 = d[i][j][2] + bb.x, v3 = d[i][j][3] + bb.y;
            if (act == 1) {
                v0 = fmaxf(v0,0.f); v1 = fmaxf(v1,0.f);
                v2 = fmaxf(v2,0.f); v3 = fmaxf(v3,0.f);
            } else if (act == 2) {
                v0 = 1.f/(1.f+__expf(-v0)); v1 = 1.f/(1.f+__expf(-v1));
                v2 = 1.f/(1.f+__expf(-v2)); v3 = 1.f/(1.f+__expf(-v3));
            }
            *(__half2*)&Co[(size_t)row*N + gcol]     = __floats2half2_rn(v0, v1);
            *(__half2*)&Co[(size_t)(row+8)*N + gcol] = __floats2half2_rn(v2, v3);
        }
    }
}

__global__ void __launch_bounds__(512) reduce_k(float* __restrict__ out)
{
    __shared__ float2 part[4][128];
    const int b = blockIdx.x, tx = threadIdx.x, ty = threadIdx.y;
    const int* __restrict__ sl = g_slot + b*NTOK + ty*64;
    float2 acc = make_float2(0.f, 0.f);
    #pragma unroll 8
    for (int t = 0; t < 64; t++) {
        int s = sl[t];
        if (s >= 0) {
            float2 fg = __half22float2(*(const __half2*)&g_G [(size_t)s*256 + 2*tx]);
            float2 fv = __half22float2(*(const __half2*)&g_Cv[(size_t)s*256 + 2*tx]);
            acc.x += fg.x * fv.x;
            acc.y += fg.y * fv.y;
        }
    }
    part[ty][tx] = acc;
    __syncthreads();
    if (ty == 0) {
        float2 r = part[0][tx];
        #pragma unroll
        for (int g = 1; g < 4; g++) { r.x += part[g][tx].x; r.y += part[g][tx].y; }
        *(float2*)&out[b*256 + 2*tx] = r;
    }
}

extern "C" void kernel_launch(void* const* d_in, const int* in_sizes, int n_in,
                              void* d_out, int out_size)
{
    const float* h0 = (const float*)d_in[0];
    const float* hT = (const float*)d_in[1];
    const float* W[8]  = { (const float*)d_in[2],  (const float*)d_in[4],
                           (const float*)d_in[6],  (const float*)d_in[8],
                           (const float*)d_in[10], (const float*)d_in[12],
                           (const float*)d_in[14], (const float*)d_in[16] };
    const float* bs[8] = { (const float*)d_in[3],  (const float*)d_in[5],
                           (const float*)d_in[7],  (const float*)d_in[9],
                           (const float*)d_in[11], (const float*)d_in[13],
                           (const float*)d_in[15], (const float*)d_in[17] };
    float* out = (float*)d_out;

    convert_w<<<(294912+255)/256, 256>>>(W[0],W[1],W[2],W[3],W[4],W[5],W[6],W[7]);
    stage1<<<MTOT/32, 1024>>>(h0, hT);

    cudaFuncSetAttribute(gemm_k, cudaFuncAttributeMaxDynamicSharedMemorySize, SMEMB);

    gemm_k<<<dim3(NT2,1,2), 256, SMEMB>>>(
        0,   0, 512,      0, 512, bs[0], 1, 1,
        0, 256, 512, 163840, 256, bs[4], 4, 1, 128);
    gemm_k<<<dim3(NT2,2,2), 256, SMEMB>>>(
        1, 0, 128,  65536, 128, bs[1], 2, 1,
        4, 0, 128, 196608, 128, bs[5], 5, 1, 256);
    gemm_k<<<dim3(NT2,1,2), 256, SMEMB>>>(
        2, 0, 256,  98304, 256, bs[2], 1, 1,
        5, 0, 256, 229376, 256, bs[6], 4, 1, 128);
    gemm_k<<<dim3(NT2,2,2), 256, SMEMB>>>(
        1, 0, 128, 131072, 128, bs[3], 3, 2,
        4, 0, 128, 262144, 128, bs[7], 5, 0, 256);

    reduce_k<<<BATCH, dim3(128,4)>>>(out);
}

// round 11
// speedup vs baseline: 1.2316x; 1.2316x over previous
#include <cuda_runtime.h>
#include <cuda_fp16.h>
#include <cstdint>

#define BATCH 512
#define NTOK  256
#define MTOT  (BATCH*NTOK)
#define NTILE (MTOT/128)

__device__ __half g_w[294912];
__device__ __half g_X [(size_t)MTOT*512];
__device__ __half g_Bg[(size_t)MTOT*128];
__device__ __half g_Cg[(size_t)MTOT*256];
__device__ __half g_G [(size_t)MTOT*256];
__device__ __half g_Bv[(size_t)MTOT*128];
__device__ __half g_Cv[(size_t)MTOT*256];
__device__ int    g_slot[MTOT];
__device__ int    g_cnt;
__device__ __half* g_bufs[6];

__constant__ int WOFF[9] = {0,65536,98304,131072,163840,196608,229376,262144,294912};

__global__ void convert_w(const float* w0,const float* w1,const float* w2,const float* w3,
                          const float* w4,const float* w5,const float* w6,const float* w7)
{
    int i = blockIdx.x*blockDim.x + threadIdx.x;
    if (i == 0) {
        g_cnt = 0;
        g_bufs[0]=g_X; g_bufs[1]=g_Bg; g_bufs[2]=g_Cg;
        g_bufs[3]=g_G; g_bufs[4]=g_Bv; g_bufs[5]=g_Cv;
    }
    if (i >= 294912) return;
    const float* p[8] = {w0,w1,w2,w3,w4,w5,w6,w7};
    int s = 0;
    while (i >= WOFF[s+1]) s++;
    g_w[i] = __float2half_rn(p[s][i - WOFF[s]]);
}

__global__ void __launch_bounds__(1024) stage1(const float* __restrict__ h0,
                                               const float* __restrict__ hT)
{
    __shared__ int flg[32], pre[32];
    int warp = threadIdx.x >> 5, lane = threadIdx.x & 31;
    int tok = blockIdx.x*32 + warp;
    const float4* p0 = (const float4*)(h0 + (size_t)tok*256);
    const float4* p1 = (const float4*)(hT + (size_t)tok*256);
    float4 a0 = p0[lane], a1 = p0[lane+32];
    float4 b0 = p1[lane], b1 = p1[lane+32];
    float s = a0.x+a0.y+a0.z+a0.w + a1.x+a1.y+a1.z+a1.w;
    #pragma unroll
    for (int o = 16; o > 0; o >>= 1) s += __shfl_xor_sync(0xffffffffu, s, o);
    int act = (s > 0.0f) ? 1 : 0;
    if (lane == 0) flg[warp] = act;
    __syncthreads();
    if (threadIdx.x == 0) {
        int tot = 0;
        for (int i = 0; i < 32; i++) { pre[i] = tot; tot += flg[i]; }
        flg[0] = atomicAdd(&g_cnt, tot);
    }
    __syncthreads();
    int slot = act ? (flg[0] + pre[warp]) : -1;
    if (lane == 0) g_slot[tok] = slot;
    if (act) {
        __half2* X = (__half2*)(g_X + (size_t)slot*512);
        X[lane*2+0]   = __floats2half2_rn(a0.x, a0.y);
        X[lane*2+1]   = __floats2half2_rn(a0.z, a0.w);
        X[64+lane*2]  = __floats2half2_rn(a1.x, a1.y);
        X[65+lane*2]  = __floats2half2_rn(a1.z, a1.w);
        X[128+lane*2] = __floats2half2_rn(b0.x, b0.y);
        X[129+lane*2] = __floats2half2_rn(b0.z, b0.w);
        X[192+lane*2] = __floats2half2_rn(b1.x, b1.y);
        X[193+lane*2] = __floats2half2_rn(b1.z, b1.w);
    }
}

__device__ __forceinline__ uint32_t s2u(const void* p) {
    uint32_t a;
    asm("{ .reg .u64 t; cvta.to.shared.u64 t, %1; cvt.u32.u64 %0, t; }" : "=r"(a) : "l"(p));
    return a;
}
#define CPA(d, s) asm volatile("cp.async.cg.shared.global [%0], [%1], 16;" :: "r"(d), "l"(s))
#define CPC() asm volatile("cp.async.commit_group;" ::: "memory")

#define LDA_S 88
#define LDB_S 136
#define SA_ST (128*LDA_S)
#define SB_ST (64*LDB_S)
#define SMEMB ((2*SA_ST + 2*SB_ST)*2)

__device__ __forceinline__ void ldmA(uint32_t* a, uint32_t addr) {
    asm volatile("ldmatrix.sync.aligned.m8n8.x4.shared.b16 {%0,%1,%2,%3}, [%4];"
        : "=r"(a[0]), "=r"(a[1]), "=r"(a[2]), "=r"(a[3]) : "r"(addr));
}
__device__ __forceinline__ void ldmB4(uint32_t* b, uint32_t addr) {
    asm volatile("ldmatrix.sync.aligned.m8n8.x4.trans.shared.b16 {%0,%1,%2,%3}, [%4];"
        : "=r"(b[0]), "=r"(b[1]), "=r"(b[2]), "=r"(b[3]) : "r"(addr));
}
__device__ __forceinline__ void mma16816(float* d, const uint32_t* a,
                                         uint32_t b0, uint32_t b1) {
    asm volatile("mma.sync.aligned.m16n8k16.row.col.f32.f16.f16.f32 "
        "{%0,%1,%2,%3},{%4,%5,%6,%7},{%8,%9},{%0,%1,%2,%3};"
        : "+f"(d[0]), "+f"(d[1]), "+f"(d[2]), "+f"(d[3])
        : "r"(a[0]), "r"(a[1]), "r"(a[2]), "r"(a[3]), "r"(b0), "r"(b1));
}

// 128x128 CTA tile, 8 warps as 2m x 4n (warp tile 64x32), BK=64, 2-stage cp.async
__global__ void __launch_bounds__(256,2) gemm_k(
    int asel0, int aoff0, int lda0, int woff0, int K0, const float* b0p, int csel0, int act0,
    int asel1, int aoff1, int lda1, int woff1, int K1, const float* b1p, int csel1, int act1,
    int N)
{
    extern __shared__ __half sm[];
    __half* sA = sm;
    __half* sB = sm + 2*SA_ST;
    int m0 = blockIdx.x * 128;
    if (m0 >= g_cnt) return;

    int asel, aoff, lda, woff, K, csel, act; const float* bias;
    if (blockIdx.z == 0) { asel=asel0; aoff=aoff0; lda=lda0; woff=woff0; K=K0; bias=b0p; csel=csel0; act=act0; }
    else                 { asel=asel1; aoff=aoff1; lda=lda1; woff=woff1; K=K1; bias=b1p; csel=csel1; act=act1; }

    const __half* __restrict__ A = g_bufs[asel] + (size_t)m0*lda + aoff;
    const __half* __restrict__ W = g_w + woff;
    __half* __restrict__ Co = g_bufs[csel];
    const int n0 = blockIdx.y * 128;
    const int tid = threadIdx.x, warp = tid >> 5, lane = tid & 31;
    const int mw = (warp >> 2) * 64;
    const int nw = (warp & 3) * 32;
    const uint32_t sAu = s2u(sA), sBu = s2u(sB);

    float d[4][4][4];
    #pragma unroll
    for (int i = 0; i < 4; i++)
        #pragma unroll
        for (int j = 0; j < 4; j++)
            #pragma unroll
            for (int e = 0; e < 4; e++) d[i][j][e] = 0.0f;

    const int nk = K >> 6;

    #define LOAD_STAGE(st, kc) do {                                                  \
        int _k0 = (kc) * 64;                                                         \
        _Pragma("unroll")                                                            \
        for (int t = 0; t < 4; t++) {                                                \
            int idx = tid + t*256;                                                   \
            int r = idx >> 3, c8 = (idx & 7) * 8;                                    \
            CPA(sAu + ((st)*SA_ST + r*LDA_S + c8)*2, A + (size_t)r*lda + _k0 + c8);  \
        }                                                                            \
        _Pragma("unroll")                                                            \
        for (int t = 0; t < 4; t++) {                                                \
            int idx = tid + t*256;                                                   \
            int r = idx >> 4, c8 = (idx & 15) * 8;                                   \
            CPA(sBu + ((st)*SB_ST + r*LDB_S + c8)*2, W + (size_t)(_k0+r)*N + n0 + c8); \
        }                                                                            \
        CPC();                                                                       \
    } while (0)

    const uint32_t aRow = mw + (lane & 7) + ((lane & 8) ? 8 : 0);
    const uint32_t aCol = (lane & 16) ? 8 : 0;
    const uint32_t aBase = sAu + (aRow * LDA_S + aCol) * 2;
    // x4.trans B: lanes 0-15 give n+0..7 (k rows 0-15), lanes 16-31 give n+8..15
    const uint32_t bBase = sBu + ((lane & 15) * LDB_S + nw + (lane >> 4) * 8) * 2;

    LOAD_STAGE(0, 0);
    for (int k = 0; k < nk; k++) {
        if (k + 1 < nk) {
            LOAD_STAGE((k+1) & 1, k+1);
            asm volatile("cp.async.wait_group 1;" ::: "memory");
        } else {
            asm volatile("cp.async.wait_group 0;" ::: "memory");
        }
        __syncthreads();
        const uint32_t aS = aBase + ((k & 1) * SA_ST) * 2;
        const uint32_t bS = bBase + ((k & 1) * SB_ST) * 2;
        #pragma unroll
        for (int kk = 0; kk < 4; kk++) {
            uint32_t af[4][4], bq[2][4];
            #pragma unroll
            for (int i = 0; i < 4; i++)
                ldmA(af[i], aS + (i*16*LDA_S + kk*16) * 2);
            #pragma unroll
            for (int jj = 0; jj < 2; jj++)
                ldmB4(bq[jj], bS + (kk*16*LDB_S + jj*16) * 2);
            #pragma unroll
            for (int i = 0; i < 4; i++)
                #pragma unroll
                for (int jj = 0; jj < 2; jj++) {
                    mma16816(d[i][jj*2  ], af[i], bq[jj][0], bq[jj][1]);
                    mma16816(d[i][jj*2+1], af[i], bq[jj][2], bq[jj][3]);
                }
        }
        __syncthreads();
    }

    #pragma unroll
    for (int i = 0; i < 4; i++) {
        int row = m0 + mw + i*16 + (lane >> 2);
        #pragma unroll
        for (int j = 0; j < 4; j++) {
            int gcol = n0 + nw + j*8 + (lane & 3)*2;
            float2 bb = *(const float2*)&bias[gcol];
            float v0 = d[i][j][0] + bb.x, v1 = d[i][j][1] + bb.y;
            float v2 = d[i][j][2] + bb.x, v3 = d[i][j][3] + bb.y;
            if (act == 1) {
                v0 = fmaxf(v0,0.f); v1 = fmaxf(v1,0.f);
                v2 = fmaxf(v2,0.f); v3 = fmaxf(v3,0.f);
            } else if (act == 2) {
                v0 = 1.f/(1.f+__expf(-v0)); v1 = 1.f/(1.f+__expf(-v1));
                v2 = 1.f/(1.f+__expf(-v2)); v3 = 1.f/(1.f+__expf(-v3));
            }
            *(__half2*)&Co[(size_t)row*N + gcol]     = __floats2half2_rn(v0, v1);
            *(__half2*)&Co[(size_t)(row+8)*N + gcol] = __floats2half2_rn(v2, v3);
        }
    }
}

__global__ void __launch_bounds__(512) reduce_k(float* __restrict__ out)
{
    __shared__ float2 part[4][128];
    const int b = blockIdx.x, tx = threadIdx.x, ty = threadIdx.y;
    const int* __restrict__ sl = g_slot + b*NTOK + ty*64;
    float2 acc = make_float2(0.f, 0.f);
    #pragma unroll 8
    for (int t = 0; t < 64; t++) {
        int s = sl[t];
        if (s >= 0) {
            float2 fg = __half22float2(*(const __half2*)&g_G [(size_t)s*256 + 2*tx]);
            float2 fv = __half22float2(*(const __half2*)&g_Cv[(size_t)s*256 + 2*tx]);
            acc.x += fg.x * fv.x;
            acc.y += fg.y * fv.y;
        }
    }
    part[ty][tx] = acc;
    __syncthreads();
    if (ty == 0) {
        float2 r = part[0][tx];
        #pragma unroll
        for (int g = 1; g < 4; g++) { r.x += part[g][tx].x; r.y += part[g][tx].y; }
        *(float2*)&out[b*256 + 2*tx] = r;
    }
}

extern "C" void kernel_launch(void* const* d_in, const int* in_sizes, int n_in,
                              void* d_out, int out_size)
{
    const float* h0 = (const float*)d_in[0];
    const float* hT = (const float*)d_in[1];
    const float* W[8]  = { (const float*)d_in[2],  (const float*)d_in[4],
                           (const float*)d_in[6],  (const float*)d_in[8],
                           (const float*)d_in[10], (const float*)d_in[12],
                           (const float*)d_in[14], (const float*)d_in[16] };
    const float* bs[8] = { (const float*)d_in[3],  (const float*)d_in[5],
                           (const float*)d_in[7],  (const float*)d_in[9],
                           (const float*)d_in[11], (const float*)d_in[13],
                           (const float*)d_in[15], (const float*)d_in[17] };
    float* out = (float*)d_out;

    convert_w<<<(294912+255)/256, 256>>>(W[0],W[1],W[2],W[3],W[4],W[5],W[6],W[7]);
    stage1<<<MTOT/32, 1024>>>(h0, hT);

    cudaFuncSetAttribute(gemm_k, cudaFuncAttributeMaxDynamicSharedMemorySize, SMEMB);

    gemm_k<<<dim3(NTILE,1,2), 256, SMEMB>>>(
        0,   0, 512,      0, 512, bs[0], 1, 1,
        0, 256, 512, 163840, 256, bs[4], 4, 1, 128);
    gemm_k<<<dim3(NTILE,2,2), 256, SMEMB>>>(
        1, 0, 128,  65536, 128, bs[1], 2, 1,
        4, 0, 128, 196608, 128, bs[5], 5, 1, 256);
    gemm_k<<<dim3(NTILE,1,2), 256, SMEMB>>>(
        2, 0, 256,  98304, 256, bs[2], 1, 1,
        5, 0, 256, 229376, 256, bs[6], 4, 1, 128);
    gemm_k<<<dim3(NTILE,2,2), 256, SMEMB>>>(
        1, 0, 128, 131072, 128, bs[3], 3, 2,
        4, 0, 128, 262144, 128, bs[7], 5, 0, 256);

    reduce_k<<<BATCH, dim3(128,4)>>>(out);
}

// round 12
// speedup vs baseline: 1.3684x; 1.1110x over previous
#include <cuda_runtime.h>
#include <cuda_fp16.h>
#include <cstdint>

#define BATCH 512
#define NTOK  256
#define MTOT  (BATCH*NTOK)
#define NTILE (MTOT/128)

__device__ __half g_w[294912];
__device__ __half g_X [(size_t)MTOT*512];
__device__ __half g_Cg[(size_t)MTOT*256];
__device__ __half g_Cv[(size_t)MTOT*256];
__device__ __half g_G [(size_t)MTOT*256];
__device__ int    g_slot[MTOT];
__device__ int    g_cnt;
__device__ __half* g_bufs[4];

__constant__ int WOFF[9] = {0,65536,98304,131072,163840,196608,229376,262144,294912};

__global__ void convert_w(const float* w0,const float* w1,const float* w2,const float* w3,
                          const float* w4,const float* w5,const float* w6,const float* w7)
{
    int i = blockIdx.x*blockDim.x + threadIdx.x;
    if (i == 0) {
        g_cnt = 0;
        g_bufs[0]=g_X; g_bufs[1]=g_Cg; g_bufs[2]=g_Cv; g_bufs[3]=g_G;
    }
    if (i >= 294912) return;
    const float* p[8] = {w0,w1,w2,w3,w4,w5,w6,w7};
    int s = 0;
    while (i >= WOFF[s+1]) s++;
    g_w[i] = __float2half_rn(p[s][i - WOFF[s]]);
}

__global__ void __launch_bounds__(1024) stage1(const float* __restrict__ h0,
                                               const float* __restrict__ hT)
{
    __shared__ int flg[32], pre[32];
    int warp = threadIdx.x >> 5, lane = threadIdx.x & 31;
    int tok = blockIdx.x*32 + warp;
    const float4* p0 = (const float4*)(h0 + (size_t)tok*256);
    const float4* p1 = (const float4*)(hT + (size_t)tok*256);
    float4 a0 = p0[lane], a1 = p0[lane+32];
    float4 b0 = p1[lane], b1 = p1[lane+32];
    float s = a0.x+a0.y+a0.z+a0.w + a1.x+a1.y+a1.z+a1.w;
    #pragma unroll
    for (int o = 16; o > 0; o >>= 1) s += __shfl_xor_sync(0xffffffffu, s, o);
    int act = (s > 0.0f) ? 1 : 0;
    if (lane == 0) flg[warp] = act;
    __syncthreads();
    if (threadIdx.x == 0) {
        int tot = 0;
        for (int i = 0; i < 32; i++) { pre[i] = tot; tot += flg[i]; }
        flg[0] = atomicAdd(&g_cnt, tot);
    }
    __syncthreads();
    int slot = act ? (flg[0] + pre[warp]) : -1;
    if (lane == 0) g_slot[tok] = slot;
    if (act) {
        __half2* X = (__half2*)(g_X + (size_t)slot*512);
        X[lane*2+0]   = __floats2half2_rn(a0.x, a0.y);
        X[lane*2+1]   = __floats2half2_rn(a0.z, a0.w);
        X[64+lane*2]  = __floats2half2_rn(a1.x, a1.y);
        X[65+lane*2]  = __floats2half2_rn(a1.z, a1.w);
        X[128+lane*2] = __floats2half2_rn(b0.x, b0.y);
        X[129+lane*2] = __floats2half2_rn(b0.z, b0.w);
        X[192+lane*2] = __floats2half2_rn(b1.x, b1.y);
        X[193+lane*2] = __floats2half2_rn(b1.z, b1.w);
    }
}

__device__ __forceinline__ uint32_t s2u(const void* p) {
    uint32_t a;
    asm("{ .reg .u64 t; cvta.to.shared.u64 t, %1; cvt.u32.u64 %0, t; }" : "=r"(a) : "l"(p));
    return a;
}
#define CPA(d, s) asm volatile("cp.async.cg.shared.global [%0], [%1], 16;" :: "r"(d), "l"(s))
#define CPC() asm volatile("cp.async.commit_group;" ::: "memory")

#define LDA_S 72     // A stage stride (halves): 144B, conflict-free, 16B aligned
#define LDB_S 136
#define LDU   136    // smem intermediate (128x128 fp16) stride
#define SA_H  (128*LDA_S)
#define SB_H  (64*LDB_S)
#define OFF_B (2*SA_H)
#define OFF_U (2*SA_H + 2*SB_H)
#define SMEMB ((2*SA_H + 2*SB_H + 128*LDU)*2)   // 106496 B -> 2 CTAs/SM

__device__ __forceinline__ void ldmA(uint32_t* a, uint32_t addr) {
    asm volatile("ldmatrix.sync.aligned.m8n8.x4.shared.b16 {%0,%1,%2,%3}, [%4];"
        : "=r"(a[0]), "=r"(a[1]), "=r"(a[2]), "=r"(a[3]) : "r"(addr));
}
__device__ __forceinline__ void ldmB4(uint32_t* b, uint32_t addr) {
    asm volatile("ldmatrix.sync.aligned.m8n8.x4.trans.shared.b16 {%0,%1,%2,%3}, [%4];"
        : "=r"(b[0]), "=r"(b[1]), "=r"(b[2]), "=r"(b[3]) : "r"(addr));
}
__device__ __forceinline__ void mma16816(float* d, const uint32_t* a,
                                         uint32_t b0, uint32_t b1) {
    asm volatile("mma.sync.aligned.m16n8k16.row.col.f32.f16.f16.f32 "
        "{%0,%1,%2,%3},{%4,%5,%6,%7},{%8,%9},{%0,%1,%2,%3};"
        : "+f"(d[0]), "+f"(d[1]), "+f"(d[2]), "+f"(d[3])
        : "r"(a[0]), "r"(a[1]), "r"(a[2]), "r"(a[3]), "r"(b0), "r"(b1));
}

// Fused two layers: Y = relu(A[128,K1] @ W1[K1,128] + b1) kept in smem,
// then Out[:, 0:256] = act2(Y @ W2[128,256] + b2) written to gmem.
__global__ void __launch_bounds__(256,2) fused2_k(
    int asel0, int aoff0, int lda0, int K10, int w1o0, const float* b1p0,
    int w2o0, const float* b2p0, int act20, int osel0,
    int asel1, int aoff1, int lda1, int K11, int w1o1, const float* b1p1,
    int w2o1, const float* b2p1, int act21, int osel1)
{
    extern __shared__ __half sm[];
    int m0 = blockIdx.x * 128;
    if (m0 >= g_cnt) return;

    int asel, aoff, lda, K1, w1o, w2o, act2, osel;
    const float *b1p, *b2p;
    if (blockIdx.z == 0) { asel=asel0; aoff=aoff0; lda=lda0; K1=K10; w1o=w1o0; b1p=b1p0;
                           w2o=w2o0; b2p=b2p0; act2=act20; osel=osel0; }
    else                 { asel=asel1; aoff=aoff1; lda=lda1; K1=K11; w1o=w1o1; b1p=b1p1;
                           w2o=w2o1; b2p=b2p1; act2=act21; osel=osel1; }

    const __half* __restrict__ A  = g_bufs[asel] + (size_t)m0*lda + aoff;
    const __half* __restrict__ W1 = g_w + w1o;
    const __half* __restrict__ W2 = g_w + w2o;
    __half* __restrict__ Co = g_bufs[osel];

    const int tid = threadIdx.x, warp = tid >> 5, lane = tid & 31;
    const int mw = (warp >> 2) * 64;
    const int nw = (warp & 3) * 32;
    const uint32_t sAu = s2u(sm);
    const uint32_t sBu = sAu + OFF_B*2;
    const uint32_t sUu = sAu + OFF_U*2;

    const uint32_t aRow = mw + (lane & 7) + ((lane & 8) ? 8 : 0);
    const uint32_t aCol = (lane & 16) ? 8 : 0;
    const uint32_t aBase  = sAu + (aRow * LDA_S + aCol) * 2;
    const uint32_t aUBase = sUu + (aRow * LDU   + aCol) * 2;
    const uint32_t bBase  = sBu + ((lane & 15) * LDB_S + nw + (lane >> 4) * 8) * 2;

    float d[4][4][4];
    #pragma unroll
    for (int i = 0; i < 4; i++)
        #pragma unroll
        for (int j = 0; j < 4; j++)
            #pragma unroll
            for (int e = 0; e < 4; e++) d[i][j][e] = 0.0f;

    // ---------------- phase 1: A(gmem) @ W1 -> U(smem), relu ----------------
    const int nk1 = K1 >> 6;

    #define LOAD_P1(st, kc) do {                                                     \
        int _k0 = (kc) * 64;                                                         \
        _Pragma("unroll")                                                            \
        for (int t = 0; t < 4; t++) {                                                \
            int idx = tid + t*256;                                                   \
            int r = idx >> 3, c8 = (idx & 7) * 8;                                    \
            CPA(sAu + ((st)*SA_H + r*LDA_S + c8)*2, A + (size_t)r*lda + _k0 + c8);   \
        }                                                                            \
        _Pragma("unroll")                                                            \
        for (int t = 0; t < 4; t++) {                                                \
            int idx = tid + t*256;                                                   \
            int r = idx >> 4, c8 = (idx & 15) * 8;                                   \
            CPA(sBu + ((st)*SB_H + r*LDB_S + c8)*2, W1 + (size_t)(_k0+r)*128 + c8);  \
        }                                                                            \
        CPC();                                                                       \
    } while (0)

    LOAD_P1(0, 0);
    for (int k = 0; k < nk1; k++) {
        if (k + 1 < nk1) {
            LOAD_P1((k+1) & 1, k+1);
            asm volatile("cp.async.wait_group 1;" ::: "memory");
        } else {
            asm volatile("cp.async.wait_group 0;" ::: "memory");
        }
        __syncthreads();
        const uint32_t aS = aBase + ((k & 1) * SA_H) * 2;
        const uint32_t bS = bBase + ((k & 1) * SB_H) * 2;
        #pragma unroll
        for (int kk = 0; kk < 4; kk++) {
            uint32_t af[4][4], bq[2][4];
            #pragma unroll
            for (int i = 0; i < 4; i++)
                ldmA(af[i], aS + (i*16*LDA_S + kk*16) * 2);
            #pragma unroll
            for (int jj = 0; jj < 2; jj++)
                ldmB4(bq[jj], bS + (kk*16*LDB_S + jj*16) * 2);
            #pragma unroll
            for (int i = 0; i < 4; i++)
                #pragma unroll
                for (int jj = 0; jj < 2; jj++) {
                    mma16816(d[i][jj*2  ], af[i], bq[jj][0], bq[jj][1]);
                    mma16816(d[i][jj*2+1], af[i], bq[jj][2], bq[jj][3]);
                }
        }
        __syncthreads();
    }

    // phase-1 epilogue: bias + relu -> U (smem), rows local to tile
    #pragma unroll
    for (int i = 0; i < 4; i++) {
        int row = mw + i*16 + (lane >> 2);
        #pragma unroll
        for (int j = 0; j < 4; j++) {
            int col = nw + j*8 + (lane & 3)*2;
            float2 bb = *(const float2*)&b1p[col];
            float v0 = fmaxf(d[i][j][0] + bb.x, 0.f);
            float v1 = fmaxf(d[i][j][1] + bb.y, 0.f);
            float v2 = fmaxf(d[i][j][2] + bb.x, 0.f);
            float v3 = fmaxf(d[i][j][3] + bb.y, 0.f);
            *(__half2*)&sm[OFF_U + row*LDU + col]     = __floats2half2_rn(v0, v1);
            *(__half2*)&sm[OFF_U + (row+8)*LDU + col] = __floats2half2_rn(v2, v3);
        }
    }
    __syncthreads();

    // ---------------- phase 2: U(smem) @ W2 -> Co(gmem), act2, N2=256 --------
    #define LOAD_P2(st, kc, pp) do {                                                 \
        int _k0 = (kc) * 64;                                                         \
        _Pragma("unroll")                                                            \
        for (int t = 0; t < 4; t++) {                                                \
            int idx = tid + t*256;                                                   \
            int r = idx >> 4, c8 = (idx & 15) * 8;                                   \
            CPA(sBu + ((st)*SB_H + r*LDB_S + c8)*2,                                  \
                W2 + (size_t)(_k0+r)*256 + (pp)*128 + c8);                           \
        }                                                                            \
        CPC();                                                                       \
    } while (0)

    for (int p = 0; p < 2; p++) {
        #pragma unroll
        for (int i = 0; i < 4; i++)
            #pragma unroll
            for (int j = 0; j < 4; j++)
                #pragma unroll
                for (int e = 0; e < 4; e++) d[i][j][e] = 0.0f;

        LOAD_P2(0, 0, p);
        for (int k = 0; k < 2; k++) {
            if (k == 0) {
                LOAD_P2(1, 1, p);
                asm volatile("cp.async.wait_group 1;" ::: "memory");
            } else {
                asm volatile("cp.async.wait_group 0;" ::: "memory");
            }
            __syncthreads();
            const uint32_t bS = bBase + (k * SB_H) * 2;
            #pragma unroll
            for (int kk = 0; kk < 4; kk++) {
                uint32_t af[4][4], bq[2][4];
                #pragma unroll
                for (int i = 0; i < 4; i++)
                    ldmA(af[i], aUBase + (i*16*LDU + k*64 + kk*16) * 2);
                #pragma unroll
                for (int jj = 0; jj < 2; jj++)
                    ldmB4(bq[jj], bS + (kk*16*LDB_S + jj*16) * 2);
                #pragma unroll
                for (int i = 0; i < 4; i++)
                    #pragma unroll
                    for (int jj = 0; jj < 2; jj++) {
                        mma16816(d[i][jj*2  ], af[i], bq[jj][0], bq[jj][1]);
                        mma16816(d[i][jj*2+1], af[i], bq[jj][2], bq[jj][3]);
                    }
            }
            __syncthreads();
        }

        #pragma unroll
        for (int i = 0; i < 4; i++) {
            int row = m0 + mw + i*16 + (lane >> 2);
            #pragma unroll
            for (int j = 0; j < 4; j++) {
                int gcol = p*128 + nw + j*8 + (lane & 3)*2;
                float2 bb = *(const float2*)&b2p[gcol];
                float v0 = d[i][j][0] + bb.x, v1 = d[i][j][1] + bb.y;
                float v2 = d[i][j][2] + bb.x, v3 = d[i][j][3] + bb.y;
                if (act2 == 1) {
                    v0 = fmaxf(v0,0.f); v1 = fmaxf(v1,0.f);
                    v2 = fmaxf(v2,0.f); v3 = fmaxf(v3,0.f);
                } else if (act2 == 2) {
                    v0 = 1.f/(1.f+__expf(-v0)); v1 = 1.f/(1.f+__expf(-v1));
                    v2 = 1.f/(1.f+__expf(-v2)); v3 = 1.f/(1.f+__expf(-v3));
                }
                *(__half2*)&Co[(size_t)row*256 + gcol]     = __floats2half2_rn(v0, v1);
                *(__half2*)&Co[(size_t)(row+8)*256 + gcol] = __floats2half2_rn(v2, v3);
            }
        }
    }
}

__global__ void __launch_bounds__(512) reduce_k(float* __restrict__ out)
{
    __shared__ float2 part[4][128];
    const int b = blockIdx.x, tx = threadIdx.x, ty = threadIdx.y;
    const int* __restrict__ sl = g_slot + b*NTOK + ty*64;
    float2 acc = make_float2(0.f, 0.f);
    #pragma unroll 8
    for (int t = 0; t < 64; t++) {
        int s = sl[t];
        if (s >= 0) {
            float2 fg = __half22float2(*(const __half2*)&g_G [(size_t)s*256 + 2*tx]);
            float2 fv = __half22float2(*(const __half2*)&g_Cv[(size_t)s*256 + 2*tx]);
            acc.x += fg.x * fv.x;
            acc.y += fg.y * fv.y;
        }
    }
    part[ty][tx] = acc;
    __syncthreads();
    if (ty == 0) {
        float2 r = part[0][tx];
        #pragma unroll
        for (int g = 1; g < 4; g++) { r.x += part[g][tx].x; r.y += part[g][tx].y; }
        *(float2*)&out[b*256 + 2*tx] = r;
    }
}

extern "C" void kernel_launch(void* const* d_in, const int* in_sizes, int n_in,
                              void* d_out, int out_size)
{
    const float* h0 = (const float*)d_in[0];
    const float* hT = (const float*)d_in[1];
    const float* W[8]  = { (const float*)d_in[2],  (const float*)d_in[4],
                           (const float*)d_in[6],  (const float*)d_in[8],
                           (const float*)d_in[10], (const float*)d_in[12],
                           (const float*)d_in[14], (const float*)d_in[16] };
    const float* bs[8] = { (const float*)d_in[3],  (const float*)d_in[5],
                           (const float*)d_in[7],  (const float*)d_in[9],
                           (const float*)d_in[11], (const float*)d_in[13],
                           (const float*)d_in[15], (const float*)d_in[17] };
    float* out = (float*)d_out;

    convert_w<<<(294912+255)/256, 256>>>(W[0],W[1],W[2],W[3],W[4],W[5],W[6],W[7]);
    stage1<<<MTOT/32, 1024>>>(h0, hT);

    cudaFuncSetAttribute(fused2_k, cudaFuncAttributeMaxDynamicSharedMemorySize, SMEMB);

    // launch 1: gate L0+L1 (X -> Cg), value L0+L1 (X.hT -> Cv)
    fused2_k<<<dim3(NTILE,1,2), 256, SMEMB>>>(
        0,   0, 512, 512,      0, bs[0],  65536, bs[1], 1, 1,
        0, 256, 512, 256, 163840, bs[4], 196608, bs[5], 1, 2);
    // launch 2: gate L2+L3 (Cg -> G, sigmoid), value L2+L3 (Cv -> Cv, linear)
    fused2_k<<<dim3(NTILE,1,2), 256, SMEMB>>>(
        1, 0, 256, 256,  98304, bs[2], 131072, bs[3], 2, 3,
        2, 0, 256, 256, 229376, bs[6], 262144, bs[7], 0, 2);

    reduce_k<<<BATCH, dim3(128,4)>>>(out);
}